// round 6
// baseline (speedup 1.0000x reference)
#include <cuda_runtime.h>
#include <cstdint>

#define NN    4096
#define NP1   4097
#define NFEAT 512
#define NHID  64
#define NCLS  16
#define NH    8
#define ALPHA 0.2f

// ---- scratch (device globals; no allocation allowed) ----
__device__ __align__(16) float g_h1[NH * NN * NHID];   // per-head projected features [h][i][c]
__device__ float g_ssrc[NH * NN];
__device__ float g_sdst[NH * NN];
__device__ __align__(16) float g_xc[NN * NH * NHID];   // concatenated layer-1 output [i][h*64+c]
__device__ __align__(16) float g_h2[NN * NCLS];
__device__ float g_s2src[NN];
__device__ float g_s2dst[NN];

// sorted scores + permutations
__device__ float g_ts1[NH * NN];
__device__ int   g_pm1[NH * NN];
__device__ float g_ts2[NN];
__device__ int   g_pm2[NN];

// cached exponentials of sorted scores (MUFU dedup: computed once in sort tail)
__device__ float g_e1a[NH * NN];   // e^{t}
__device__ float g_e1b[NH * NN];   // e^{ALPHA t}
__device__ float g_e2a[NN];
__device__ float g_e2b[NN];

// scans: E_suf[r][c] = sum_{k>=r} e^{t_k} h[perm_k][c]; F_pre[r][c] = sum_{k<r} e^{.2 t_k} h[perm_k][c]
__device__ float g_E1[NH * NP1 * NHID];
__device__ float g_F1[NH * NP1 * NHID];
__device__ float g_es1[NH * NP1];
__device__ float g_fs1[NH * NP1];
__device__ float g_E2[NP1 * NCLS];
__device__ float g_F2[NP1 * NCLS];
__device__ float g_es2[NP1];
__device__ float g_fs2[NP1];

__device__ __forceinline__ float elu1(float v) { return v > 0.f ? v : __expf(v) - 1.f; }

// packed f32x2 helpers (sm_103a FFMA2 path; see SASS_QUICKREF "fma.rn.f32x2")
__device__ __forceinline__ unsigned long long pack_dup(float a) {
    unsigned long long r;
    asm("mov.b64 %0, {%1, %1};" : "=l"(r) : "r"(__float_as_uint(a)));
    return r;
}
__device__ __forceinline__ void fma2(unsigned long long& acc, unsigned long long a, unsigned long long b) {
    asm("fma.rn.f32x2 %0, %1, %2, %0;" : "+l"(acc) : "l"(a), "l"(b));
}

// ============================================================
// Kernel 1: h1[h] = x @ Wh[h]  as one 4096x512x512 GEMM
// (cols = head-major concat). 128x128 tile, 256 threads,
// 8x8 microtile via packed fma.rn.f32x2. k-tile 16, reg prefetch.
// FUSED: s_src/s_dst score dots computed in the epilogue
// (8-lane shfl reduction; removes scores1 kernel + 16MB reread).
// ============================================================
__global__ __launch_bounds__(256) void gemm1_kernel(const float* __restrict__ x,
                                                    const float* __restrict__ Wh,
                                                    const float* __restrict__ ah) {
    __shared__ __align__(16) float sxT[16][132];   // [k][row]
    __shared__ __align__(16) float sW[16][132];    // [k][col]
    const int r0 = blockIdx.x * 128;
    const int by = blockIdx.y;       // col tile: heads 2*by, 2*by+1
    const int tid = threadIdx.x;
    const int tx = tid & 15, ty = tid >> 4;   // 8 cols per tx, 8 rows per ty

    unsigned long long acc[8][4] = {};   // [row][colpair]

    // prefetch tile 0
    float4 px0, px1, pw0, pw1;
    {
        int e0 = tid, e1 = tid + 256;
        int r_ = e0 >> 2, kq = e0 & 3;
        px0 = *(const float4*)&x[(r0 + r_) * NFEAT + kq * 4];
        r_ = e1 >> 2; kq = e1 & 3;
        px1 = *(const float4*)&x[(r0 + r_) * NFEAT + kq * 4];
        int k_ = e0 >> 5, cq = e0 & 31;
        pw0 = *(const float4*)&Wh[((2 * by + (cq >> 4)) * NFEAT + k_) * NHID + (cq & 15) * 4];
        k_ = e1 >> 5; cq = e1 & 31;
        pw1 = *(const float4*)&Wh[((2 * by + (cq >> 4)) * NFEAT + k_) * NHID + (cq & 15) * 4];
    }

    for (int kt = 0; kt < NFEAT / 16; kt++) {
        __syncthreads();
        // store prefetched tile
        {
            int e0 = tid, e1 = tid + 256;
            int r_ = e0 >> 2, kq = e0 & 3;
            sxT[kq * 4 + 0][r_] = px0.x; sxT[kq * 4 + 1][r_] = px0.y;
            sxT[kq * 4 + 2][r_] = px0.z; sxT[kq * 4 + 3][r_] = px0.w;
            r_ = e1 >> 2; kq = e1 & 3;
            sxT[kq * 4 + 0][r_] = px1.x; sxT[kq * 4 + 1][r_] = px1.y;
            sxT[kq * 4 + 2][r_] = px1.z; sxT[kq * 4 + 3][r_] = px1.w;
            int k_ = e0 >> 5, cq = e0 & 31;
            *(float4*)&sW[k_][cq * 4] = pw0;
            k_ = e1 >> 5; cq = e1 & 31;
            *(float4*)&sW[k_][cq * 4] = pw1;
        }
        __syncthreads();
        // prefetch next tile (LDG latency hidden under compute)
        if (kt + 1 < NFEAT / 16) {
            int k0 = (kt + 1) * 16;
            int e0 = tid, e1 = tid + 256;
            int r_ = e0 >> 2, kq = e0 & 3;
            px0 = *(const float4*)&x[(r0 + r_) * NFEAT + k0 + kq * 4];
            r_ = e1 >> 2; kq = e1 & 3;
            px1 = *(const float4*)&x[(r0 + r_) * NFEAT + k0 + kq * 4];
            int k_ = e0 >> 5, cq = e0 & 31;
            pw0 = *(const float4*)&Wh[((2 * by + (cq >> 4)) * NFEAT + k0 + k_) * NHID + (cq & 15) * 4];
            k_ = e1 >> 5; cq = e1 & 31;
            pw1 = *(const float4*)&Wh[((2 * by + (cq >> 4)) * NFEAT + k0 + k_) * NHID + (cq & 15) * 4];
        }
        // compute 16 k-steps
        #pragma unroll
        for (int k = 0; k < 16; k++) {
            float4 a03 = *(const float4*)&sxT[k][ty * 8];
            float4 a47 = *(const float4*)&sxT[k][ty * 8 + 4];
            ulonglong2 bA = *(const ulonglong2*)&sW[k][tx * 8];      // (b0,b1),(b2,b3)
            ulonglong2 bB = *(const ulonglong2*)&sW[k][tx * 8 + 4];  // (b4,b5),(b6,b7)
            unsigned long long pa[8];
            pa[0] = pack_dup(a03.x); pa[1] = pack_dup(a03.y);
            pa[2] = pack_dup(a03.z); pa[3] = pack_dup(a03.w);
            pa[4] = pack_dup(a47.x); pa[5] = pack_dup(a47.y);
            pa[6] = pack_dup(a47.z); pa[7] = pack_dup(a47.w);
            #pragma unroll
            for (int i = 0; i < 8; i++) {
                fma2(acc[i][0], pa[i], bA.x);
                fma2(acc[i][1], pa[i], bA.y);
                fma2(acc[i][2], pa[i], bB.x);
                fma2(acc[i][3], pa[i], bB.y);
            }
        }
    }

    // epilogue: unpack + write g_h1[h][r][c] + fused score dots
    const int head = 2 * by + (tx >> 3);
    const int cb = (tx * 8) & 63;
    // attention vector slices for this thread's 8 columns
    float4 as0 = *(const float4*)&ah[head * 2 * NHID + cb];
    float4 as1 = *(const float4*)&ah[head * 2 * NHID + cb + 4];
    float4 ad0 = *(const float4*)&ah[head * 2 * NHID + NHID + cb];
    float4 ad1 = *(const float4*)&ah[head * 2 * NHID + NHID + cb + 4];
    #pragma unroll
    for (int i = 0; i < 8; i++) {
        int r = r0 + ty * 8 + i;
        float4 lo, hi;
        lo.x = __uint_as_float((unsigned)acc[i][0]);  lo.y = __uint_as_float((unsigned)(acc[i][0] >> 32));
        lo.z = __uint_as_float((unsigned)acc[i][1]);  lo.w = __uint_as_float((unsigned)(acc[i][1] >> 32));
        hi.x = __uint_as_float((unsigned)acc[i][2]);  hi.y = __uint_as_float((unsigned)(acc[i][2] >> 32));
        hi.z = __uint_as_float((unsigned)acc[i][3]);  hi.w = __uint_as_float((unsigned)(acc[i][3] >> 32));
        *(float4*)&g_h1[(head * NN + r) * NHID + cb]     = lo;
        *(float4*)&g_h1[(head * NN + r) * NHID + cb + 4] = hi;
        // partial score dots over this thread's 8 cols
        float ss = lo.x*as0.x + lo.y*as0.y + lo.z*as0.z + lo.w*as0.w
                 + hi.x*as1.x + hi.y*as1.y + hi.z*as1.z + hi.w*as1.w;
        float sd = lo.x*ad0.x + lo.y*ad0.y + lo.z*ad0.z + lo.w*ad0.w
                 + hi.x*ad1.x + hi.y*ad1.y + hi.z*ad1.z + hi.w*ad1.w;
        // reduce across the 8 lanes owning this (head,row): lanes are a
        // contiguous aligned 8-group within the warp (lane = (ty&1)*16 + tx)
        #pragma unroll
        for (int o = 4; o; o >>= 1) {
            ss += __shfl_xor_sync(0xffffffffu, ss, o);
            sd += __shfl_xor_sync(0xffffffffu, sd, o);
        }
        if ((tx & 7) == 0) {
            g_ssrc[head * NN + r] = ss;
            g_sdst[head * NN + r] = sd;
        }
    }
}

// ============================================================
// Bitonic sort of 4096 (value, index) pairs in shared memory
// ============================================================
__device__ __forceinline__ void bitonic4096(float* sv, int* si_, int tid) {
    for (int k = 2; k <= 4096; k <<= 1) {
        for (int j = k >> 1; j > 0; j >>= 1) {
            #pragma unroll
            for (int q = 0; q < 4; q++) {
                int i = tid + q * 1024;
                int ixj = i ^ j;
                if (ixj > i) {
                    bool up = ((i & k) == 0);
                    float a = sv[i], b = sv[ixj];
                    if ((a > b) == up) {
                        sv[i] = b; sv[ixj] = a;
                        int ta = si_[i]; si_[i] = si_[ixj]; si_[ixj] = ta;
                    }
                }
            }
            __syncthreads();
        }
    }
}

// sort + fused exp-cache write (removes separate exp kernels)
__global__ __launch_bounds__(1024) void sort1_kernel() {
    __shared__ float sv[4096];
    __shared__ int   si_[4096];
    const int h = blockIdx.x, tid = threadIdx.x;
    for (int i = tid; i < 4096; i += 1024) { sv[i] = g_sdst[h * NN + i]; si_[i] = i; }
    __syncthreads();
    bitonic4096(sv, si_, tid);
    for (int i = tid; i < 4096; i += 1024) {
        float t = sv[i];
        g_ts1[h * NN + i] = t;
        g_pm1[h * NN + i] = si_[i];
        g_e1a[h * NN + i] = __expf(t);
        g_e1b[h * NN + i] = __expf(ALPHA * t);
    }
}

__global__ __launch_bounds__(1024) void sort2_kernel() {
    __shared__ float sv[4096];
    __shared__ int   si_[4096];
    const int tid = threadIdx.x;
    for (int i = tid; i < 4096; i += 1024) { sv[i] = g_s2dst[i]; si_[i] = i; }
    __syncthreads();
    bitonic4096(sv, si_, tid);
    for (int i = tid; i < 4096; i += 1024) {
        float t = sv[i];
        g_ts2[i] = t;
        g_pm2[i] = si_[i];
        g_e2a[i] = __expf(t);
        g_e2b[i] = __expf(ALPHA * t);
    }
}

// ============================================================
// Warp-parallel chunk-offset scan helper (threads 0..31).
// ============================================================
__device__ __forceinline__ void chunk_offsets(const float* totA, const float* totB,
                                              float* offA, float* offB, int tid) {
    if (tid < 32) {
        float pb[8], pa[8];
        float sb = 0.f, sa = 0.f;
        #pragma unroll
        for (int j = 0; j < 8; j++) { sb += totB[tid * 8 + j]; pb[j] = sb; }
        #pragma unroll
        for (int j = 7; j >= 0; j--) { sa += totA[tid * 8 + j]; pa[j] = sa; }
        float eb = sb;
        #pragma unroll
        for (int o = 1; o < 32; o <<= 1) {
            float t = __shfl_up_sync(0xffffffffu, eb, o);
            if (tid >= o) eb += t;
        }
        eb -= sb;
        float ea = sa;
        #pragma unroll
        for (int o = 1; o < 32; o <<= 1) {
            float t = __shfl_down_sync(0xffffffffu, ea, o);
            if (tid + o < 32) ea += t;
        }
        ea -= sa;
        #pragma unroll
        for (int j = 0; j < 8; j++) {
            offB[tid * 8 + j + 1] = eb + pb[j];
            offA[tid * 8 + j]     = ea + pa[j];
        }
        if (tid == 0)  offB[0]   = 0.f;
        if (tid == 31) offA[256] = 0.f;
    }
}

// ============================================================
// Scan kernels: per (head, col) E_suf / F_pre over sorted order.
// ============================================================
__global__ void scan1_kernel() {
    const int h = blockIdx.x / (NHID + 1);
    const int c = blockIdx.x % (NHID + 1);
    const int tid = threadIdx.x;
    __shared__ float totA[256], totB[256];
    __shared__ float offA[257], offB[257];
    float a_loc[16], b_loc[16];
    const int base = tid * 16;
    #pragma unroll
    for (int q = 0; q < 16; q++) {
        int k = base + q;
        float hv = 1.0f;
        if (c < NHID) hv = g_h1[(h * NN + g_pm1[h * NN + k]) * NHID + c];
        a_loc[q] = g_e1a[h * NN + k] * hv;
        b_loc[q] = g_e1b[h * NN + k] * hv;
    }
    #pragma unroll
    for (int q = 1; q < 16; q++) b_loc[q] += b_loc[q - 1];
    #pragma unroll
    for (int q = 14; q >= 0; q--) a_loc[q] += a_loc[q + 1];
    totB[tid] = b_loc[15]; totA[tid] = a_loc[0];
    __syncthreads();
    chunk_offsets(totA, totB, offA, offB, tid);
    __syncthreads();
    const float ob = offB[tid];
    const float oa = offA[tid + 1];
    if (c < NHID) {
        float* E = g_E1 + (h * NP1) * NHID + c;
        float* F = g_F1 + (h * NP1) * NHID + c;
        #pragma unroll
        for (int q = 0; q < 16; q++) {
            E[(base + q) * NHID]     = a_loc[q] + oa;
            F[(base + q + 1) * NHID] = b_loc[q] + ob;
        }
        if (tid == 0)   F[0] = 0.f;
        if (tid == 255) E[NN * NHID] = 0.f;
    } else {
        float* e = g_es1 + h * NP1;
        float* f = g_fs1 + h * NP1;
        #pragma unroll
        for (int q = 0; q < 16; q++) {
            e[base + q]     = a_loc[q] + oa;
            f[base + q + 1] = b_loc[q] + ob;
        }
        if (tid == 0)   f[0] = 0.f;
        if (tid == 255) e[NN] = 0.f;
    }
}

__global__ void scan2_kernel() {
    const int c = blockIdx.x;
    const int tid = threadIdx.x;
    __shared__ float totA[256], totB[256];
    __shared__ float offA[257], offB[257];
    float a_loc[16], b_loc[16];
    const int base = tid * 16;
    #pragma unroll
    for (int q = 0; q < 16; q++) {
        int k = base + q;
        float hv = 1.0f;
        if (c < NCLS) hv = g_h2[g_pm2[k] * NCLS + c];
        a_loc[q] = g_e2a[k] * hv;
        b_loc[q] = g_e2b[k] * hv;
    }
    #pragma unroll
    for (int q = 1; q < 16; q++) b_loc[q] += b_loc[q - 1];
    #pragma unroll
    for (int q = 14; q >= 0; q--) a_loc[q] += a_loc[q + 1];
    totB[tid] = b_loc[15]; totA[tid] = a_loc[0];
    __syncthreads();
    chunk_offsets(totA, totB, offA, offB, tid);
    __syncthreads();
    const float ob = offB[tid];
    const float oa = offA[tid + 1];
    if (c < NCLS) {
        float* E = g_E2 + c;
        float* F = g_F2 + c;
        #pragma unroll
        for (int q = 0; q < 16; q++) {
            E[(base + q) * NCLS]     = a_loc[q] + oa;
            F[(base + q + 1) * NCLS] = b_loc[q] + ob;
        }
        if (tid == 0)   F[0] = 0.f;
        if (tid == 255) E[NN * NCLS] = 0.f;
    } else {
        #pragma unroll
        for (int q = 0; q < 16; q++) {
            g_es2[base + q]     = a_loc[q] + oa;
            g_fs2[base + q + 1] = b_loc[q] + ob;
        }
        if (tid == 0)   g_fs2[0] = 0.f;
        if (tid == 255) g_es2[NN] = 0.f;
    }
}

// ============================================================
// Row kernels: binary search rank, combine scans, normalize.
// 64 rows per block, 8 rows per warp. Row exps computed once
// on lanes 0..7 and shfl-broadcast (MUFU dedup).
// ============================================================
__global__ void row1_kernel() {
    __shared__ float st[4096];
    const int h = blockIdx.y;
    const int warp = threadIdx.x >> 5, lane = threadIdx.x & 31;
    for (int q = threadIdx.x; q < 4096; q += 256) st[q] = g_ts1[h * NN + q];
    __syncthreads();
    const int row_l = blockIdx.x * 64 + warp * 8 + (lane & 7);
    const float s_l  = g_ssrc[h * NN + row_l];
    const float w1_l = __expf(s_l);
    const float w2_l = __expf(ALPHA * s_l);
    for (int rr = 0; rr < 8; rr++) {
        const int i = blockIdx.x * 64 + warp * 8 + rr;
        const float si = __shfl_sync(0xffffffffu, s_l, rr);
        const float w1 = __shfl_sync(0xffffffffu, w1_l, rr);
        const float w2 = __shfl_sync(0xffffffffu, w2_l, rr);
        const float thr = -si;
        int lo = 0, hi = 4096;
        while (lo < hi) { int mid = (lo + hi) >> 1; if (st[mid] <= thr) lo = mid + 1; else hi = mid; }
        const int r = lo;
        const float den = w1 * g_es1[h * NP1 + r] + w2 * g_fs1[h * NP1 + r];
        const float invden = 1.f / den;
        const float* E = g_E1 + (h * NP1 + r) * NHID;
        const float* F = g_F1 + (h * NP1 + r) * NHID;
        #pragma unroll
        for (int c = lane; c < NHID; c += 32) {
            float v = (w1 * E[c] + w2 * F[c]) * invden;
            g_xc[i * (NH * NHID) + h * NHID + c] = elu1(v);
        }
    }
}

__global__ void row2_kernel(float* __restrict__ out) {
    __shared__ float st[4096];
    const int warp = threadIdx.x >> 5, lane = threadIdx.x & 31;
    for (int q = threadIdx.x; q < 4096; q += 256) st[q] = g_ts2[q];
    __syncthreads();
    const int row_l = blockIdx.x * 64 + warp * 8 + (lane & 7);
    const float s_l  = g_s2src[row_l];
    const float w1_l = __expf(s_l);
    const float w2_l = __expf(ALPHA * s_l);
    for (int rr = 0; rr < 8; rr++) {
        const int i = blockIdx.x * 64 + warp * 8 + rr;
        const float si = __shfl_sync(0xffffffffu, s_l, rr);
        const float w1 = __shfl_sync(0xffffffffu, w1_l, rr);
        const float w2 = __shfl_sync(0xffffffffu, w2_l, rr);
        const float thr = -si;
        int lo = 0, hi = 4096;
        while (lo < hi) { int mid = (lo + hi) >> 1; if (st[mid] <= thr) lo = mid + 1; else hi = mid; }
        const int r = lo;
        const float den = w1 * g_es2[r] + w2 * g_fs2[r];
        const float invden = 1.f / den;
        float v = -1e30f;
        if (lane < NCLS)
            v = elu1((w1 * g_E2[r * NCLS + lane] + w2 * g_F2[r * NCLS + lane]) * invden);
        float m = v;
        #pragma unroll
        for (int o = 8; o; o >>= 1) m = fmaxf(m, __shfl_xor_sync(0xffffffffu, m, o));
        float s = __expf(v - m);
        #pragma unroll
        for (int o = 8; o; o >>= 1) s += __shfl_xor_sync(0xffffffffu, s, o);
        const float lse = m + __logf(s);
        if (lane < NCLS) out[i * NCLS + lane] = v - lse;
    }
}

// ============================================================
// Kernel: h2 = xc @ Wo (4096x512 @ 512x16) + layer-2 score dots
// ============================================================
__global__ void gemm2_kernel(const float* __restrict__ Wo, const float* __restrict__ ao) {
    __shared__ __align__(16) float sxcT[32][68];
    __shared__ __align__(16) float sWo[32][20];
    __shared__ __align__(16) float sh2s[64][17];
    const int r0 = blockIdx.x * 64;
    const int tid = threadIdx.x;
    const int c4 = tid & 3, r = tid >> 2;
    float acc[4] = {};

    for (int k0 = 0; k0 < NFEAT; k0 += 32) {
        __syncthreads();
        #pragma unroll
        for (int i = tid; i < 2048; i += 256) {
            int k = i & 31, rr = i >> 5;
            sxcT[k][rr] = g_xc[(r0 + rr) * NFEAT + k0 + k];
        }
        #pragma unroll
        for (int i = tid; i < 512; i += 256) {
            int k = i >> 4, c = i & 15;
            sWo[k][c] = Wo[(k0 + k) * NCLS + c];
        }
        __syncthreads();
        #pragma unroll
        for (int k = 0; k < 32; k++) {
            float a = sxcT[k][r];
            float4 b = *(const float4*)&sWo[k][c4 * 4];
            acc[0] += a * b.x; acc[1] += a * b.y; acc[2] += a * b.z; acc[3] += a * b.w;
        }
    }
    *(float4*)&g_h2[(r0 + r) * NCLS + c4 * 4] = make_float4(acc[0], acc[1], acc[2], acc[3]);
    sh2s[r][c4 * 4 + 0] = acc[0];
    sh2s[r][c4 * 4 + 1] = acc[1];
    sh2s[r][c4 * 4 + 2] = acc[2];
    sh2s[r][c4 * 4 + 3] = acc[3];
    __syncthreads();
    if (tid < 64) {
        float ss = 0.f, sd = 0.f;
        #pragma unroll
        for (int c = 0; c < NCLS; c++) {
            float hv = sh2s[tid][c];
            ss += hv * ao[c];
            sd += hv * ao[NCLS + c];
        }
        g_s2src[r0 + tid] = ss;
        g_s2dst[r0 + tid] = sd;
    }
}

// ============================================================
extern "C" void kernel_launch(void* const* d_in, const int* in_sizes, int n_in,
                              void* d_out, int out_size) {
    const float* x  = (const float*)d_in[0];
    const float* Wh = (const float*)d_in[1];
    const float* ah = (const float*)d_in[2];
    const float* Wo = (const float*)d_in[3];
    const float* ao = (const float*)d_in[4];
    float* out = (float*)d_out;

    gemm1_kernel<<<dim3(NN / 128, 4), 256>>>(x, Wh, ah);
    sort1_kernel<<<NH, 1024>>>();
    scan1_kernel<<<NH * (NHID + 1), 256>>>();
    row1_kernel<<<dim3(NN / 64, NH), 256>>>();
    gemm2_kernel<<<NN / 64, 256>>>(Wo, ao);
    sort2_kernel<<<1, 1024>>>();
    scan2_kernel<<<NCLS + 1, 256>>>();
    row2_kernel<<<NN / 64, 256>>>(out);
}

// round 7
// speedup vs baseline: 1.2226x; 1.2226x over previous
#include <cuda_runtime.h>
#include <cstdint>

#define NN    4096
#define NP1   4097
#define NFEAT 512
#define NHID  64
#define NCLS  16
#define NH    8
#define ALPHA 0.2f
#define TILE  128
#define NT    (NN / TILE)   // 32

// ---- scratch (device globals; no allocation allowed) ----
__device__ __align__(16) float g_h1[NH * NN * NHID];
__device__ float g_ssrc[NH * NN];
__device__ float g_sdst[NH * NN];
__device__ __align__(16) float g_xc[NN * NH * NHID];
__device__ __align__(16) float g_h2[NN * NCLS];
__device__ float g_s2src[NN];
__device__ float g_s2dst[NN];

// sorted scores + permutations + exp caches (written by sort tails)
__device__ float g_ts1[NH * NN];
__device__ int   g_pm1[NH * NN];
__device__ float g_e1a[NH * NN];
__device__ float g_e1b[NH * NN];
__device__ float g_ts2[NN];
__device__ int   g_pm2[NN];
__device__ float g_e2a[NN];
__device__ float g_e2b[NN];

// layer-1 scans, [h][r][c] row-contiguous; within-tile values + cross-tile offsets
__device__ __align__(16) float g_E1[NH * NP1 * NHID];
__device__ __align__(16) float g_F1[NH * NP1 * NHID];
__device__ float g_totA[NH * NT * NHID];
__device__ float g_totB[NH * NT * NHID];
__device__ float g_offE[NH * (NT + 1) * NHID];
__device__ float g_offF[NH * (NT + 1) * NHID];
__device__ float g_es1[NH * NP1];
__device__ float g_fs1[NH * NP1];

// layer-2 scans
__device__ float g_E2[NP1 * NCLS];
__device__ float g_F2[NP1 * NCLS];
__device__ float g_es2[NP1];
__device__ float g_fs2[NP1];

__device__ __forceinline__ float elu1(float v) { return v > 0.f ? v : __expf(v) - 1.f; }

// packed f32x2 helpers (sm_103a FFMA2 path)
__device__ __forceinline__ unsigned long long pack_dup(float a) {
    unsigned long long r;
    asm("mov.b64 %0, {%1, %1};" : "=l"(r) : "r"(__float_as_uint(a)));
    return r;
}
__device__ __forceinline__ void fma2(unsigned long long& acc, unsigned long long a, unsigned long long b) {
    asm("fma.rn.f32x2 %0, %1, %2, %0;" : "+l"(acc) : "l"(a), "l"(b));
}

// ============================================================
// Kernel 1: h1 = x @ Wh (fused per-row score dots in epilogue)
// ============================================================
__global__ __launch_bounds__(256) void gemm1_kernel(const float* __restrict__ x,
                                                    const float* __restrict__ Wh,
                                                    const float* __restrict__ ah) {
    __shared__ __align__(16) float sxT[16][132];
    __shared__ __align__(16) float sW[16][132];
    const int r0 = blockIdx.x * 128;
    const int by = blockIdx.y;
    const int tid = threadIdx.x;
    const int tx = tid & 15, ty = tid >> 4;

    unsigned long long acc[8][4] = {};

    float4 px0, px1, pw0, pw1;
    {
        int e0 = tid, e1 = tid + 256;
        int r_ = e0 >> 2, kq = e0 & 3;
        px0 = *(const float4*)&x[(r0 + r_) * NFEAT + kq * 4];
        r_ = e1 >> 2; kq = e1 & 3;
        px1 = *(const float4*)&x[(r0 + r_) * NFEAT + kq * 4];
        int k_ = e0 >> 5, cq = e0 & 31;
        pw0 = *(const float4*)&Wh[((2 * by + (cq >> 4)) * NFEAT + k_) * NHID + (cq & 15) * 4];
        k_ = e1 >> 5; cq = e1 & 31;
        pw1 = *(const float4*)&Wh[((2 * by + (cq >> 4)) * NFEAT + k_) * NHID + (cq & 15) * 4];
    }

    for (int kt = 0; kt < NFEAT / 16; kt++) {
        __syncthreads();
        {
            int e0 = tid, e1 = tid + 256;
            int r_ = e0 >> 2, kq = e0 & 3;
            sxT[kq * 4 + 0][r_] = px0.x; sxT[kq * 4 + 1][r_] = px0.y;
            sxT[kq * 4 + 2][r_] = px0.z; sxT[kq * 4 + 3][r_] = px0.w;
            r_ = e1 >> 2; kq = e1 & 3;
            sxT[kq * 4 + 0][r_] = px1.x; sxT[kq * 4 + 1][r_] = px1.y;
            sxT[kq * 4 + 2][r_] = px1.z; sxT[kq * 4 + 3][r_] = px1.w;
            int k_ = e0 >> 5, cq = e0 & 31;
            *(float4*)&sW[k_][cq * 4] = pw0;
            k_ = e1 >> 5; cq = e1 & 31;
            *(float4*)&sW[k_][cq * 4] = pw1;
        }
        __syncthreads();
        if (kt + 1 < NFEAT / 16) {
            int k0 = (kt + 1) * 16;
            int e0 = tid, e1 = tid + 256;
            int r_ = e0 >> 2, kq = e0 & 3;
            px0 = *(const float4*)&x[(r0 + r_) * NFEAT + k0 + kq * 4];
            r_ = e1 >> 2; kq = e1 & 3;
            px1 = *(const float4*)&x[(r0 + r_) * NFEAT + k0 + kq * 4];
            int k_ = e0 >> 5, cq = e0 & 31;
            pw0 = *(const float4*)&Wh[((2 * by + (cq >> 4)) * NFEAT + k0 + k_) * NHID + (cq & 15) * 4];
            k_ = e1 >> 5; cq = e1 & 31;
            pw1 = *(const float4*)&Wh[((2 * by + (cq >> 4)) * NFEAT + k0 + k_) * NHID + (cq & 15) * 4];
        }
        #pragma unroll
        for (int k = 0; k < 16; k++) {
            float4 a03 = *(const float4*)&sxT[k][ty * 8];
            float4 a47 = *(const float4*)&sxT[k][ty * 8 + 4];
            ulonglong2 bA = *(const ulonglong2*)&sW[k][tx * 8];
            ulonglong2 bB = *(const ulonglong2*)&sW[k][tx * 8 + 4];
            unsigned long long pa[8];
            pa[0] = pack_dup(a03.x); pa[1] = pack_dup(a03.y);
            pa[2] = pack_dup(a03.z); pa[3] = pack_dup(a03.w);
            pa[4] = pack_dup(a47.x); pa[5] = pack_dup(a47.y);
            pa[6] = pack_dup(a47.z); pa[7] = pack_dup(a47.w);
            #pragma unroll
            for (int i = 0; i < 8; i++) {
                fma2(acc[i][0], pa[i], bA.x);
                fma2(acc[i][1], pa[i], bA.y);
                fma2(acc[i][2], pa[i], bB.x);
                fma2(acc[i][3], pa[i], bB.y);
            }
        }
    }

    const int head = 2 * by + (tx >> 3);
    const int cb = (tx * 8) & 63;
    float4 as0 = *(const float4*)&ah[head * 2 * NHID + cb];
    float4 as1 = *(const float4*)&ah[head * 2 * NHID + cb + 4];
    float4 ad0 = *(const float4*)&ah[head * 2 * NHID + NHID + cb];
    float4 ad1 = *(const float4*)&ah[head * 2 * NHID + NHID + cb + 4];
    #pragma unroll
    for (int i = 0; i < 8; i++) {
        int r = r0 + ty * 8 + i;
        float4 lo, hi;
        lo.x = __uint_as_float((unsigned)acc[i][0]);  lo.y = __uint_as_float((unsigned)(acc[i][0] >> 32));
        lo.z = __uint_as_float((unsigned)acc[i][1]);  lo.w = __uint_as_float((unsigned)(acc[i][1] >> 32));
        hi.x = __uint_as_float((unsigned)acc[i][2]);  hi.y = __uint_as_float((unsigned)(acc[i][2] >> 32));
        hi.z = __uint_as_float((unsigned)acc[i][3]);  hi.w = __uint_as_float((unsigned)(acc[i][3] >> 32));
        *(float4*)&g_h1[(head * NN + r) * NHID + cb]     = lo;
        *(float4*)&g_h1[(head * NN + r) * NHID + cb + 4] = hi;
        float ss = lo.x*as0.x + lo.y*as0.y + lo.z*as0.z + lo.w*as0.w
                 + hi.x*as1.x + hi.y*as1.y + hi.z*as1.z + hi.w*as1.w;
        float sd = lo.x*ad0.x + lo.y*ad0.y + lo.z*ad0.z + lo.w*ad0.w
                 + hi.x*ad1.x + hi.y*ad1.y + hi.z*ad1.z + hi.w*ad1.w;
        #pragma unroll
        for (int o = 4; o; o >>= 1) {
            ss += __shfl_xor_sync(0xffffffffu, ss, o);
            sd += __shfl_xor_sync(0xffffffffu, sd, o);
        }
        if ((tx & 7) == 0) {
            g_ssrc[head * NN + r] = ss;
            g_sdst[head * NN + r] = sd;
        }
    }
}

// ============================================================
// Bitonic sort (warp-local shfl for j<=16) + fused exp caches
// + fused scalar prefix/suffix scans (es/fs) in the tail.
// ============================================================
__device__ void sortex_body(float* sv, int* si_, float* wtA, float* wtB,
                            const float* __restrict__ src,
                            float* ts, int* pm, float* ea_o, float* eb_o,
                            float* es_, float* fs_) {
    const int tid = threadIdx.x, lane = tid & 31, w = tid >> 5;
    for (int i = tid; i < 4096; i += 1024) { sv[i] = src[i]; si_[i] = i; }
    __syncthreads();

    // fused warp-local stages k = 2..32 (one register session per group)
    #pragma unroll
    for (int gg = 0; gg < 4; gg++) {
        int g = w * 4 + gg, i = g * 32 + lane;
        float v = sv[i]; int id = si_[i];
        #pragma unroll
        for (int k = 2; k <= 32; k <<= 1) {
            bool up = ((i & k) == 0);
            #pragma unroll
            for (int j = k >> 1; j; j >>= 1) {
                float ov = __shfl_xor_sync(0xffffffffu, v, j);
                int   oi = __shfl_xor_sync(0xffffffffu, id, j);
                bool lower = (lane & j) == 0;
                bool agtb = lower ? (v > ov) : (ov > v);
                if (agtb == up) { v = ov; id = oi; }
            }
        }
        sv[i] = v; si_[i] = id;
    }
    __syncthreads();

    for (int k = 64; k <= 4096; k <<= 1) {
        for (int j = k >> 1; j >= 32; j >>= 1) {
            #pragma unroll
            for (int q = 0; q < 4; q++) {
                int i = tid + q * 1024;
                int ixj = i ^ j;
                if (ixj > i) {
                    bool up = ((i & k) == 0);
                    float a = sv[i], b = sv[ixj];
                    if ((a > b) == up) {
                        sv[i] = b; sv[ixj] = a;
                        int t = si_[i]; si_[i] = si_[ixj]; si_[ixj] = t;
                    }
                }
            }
            __syncthreads();
        }
        #pragma unroll
        for (int gg = 0; gg < 4; gg++) {
            int g = w * 4 + gg, i = g * 32 + lane;
            float v = sv[i]; int id = si_[i];
            bool up = ((i & k) == 0);
            #pragma unroll
            for (int j = 16; j; j >>= 1) {
                float ov = __shfl_xor_sync(0xffffffffu, v, j);
                int   oi = __shfl_xor_sync(0xffffffffu, id, j);
                bool lower = (lane & j) == 0;
                bool agtb = lower ? (v > ov) : (ov > v);
                if (agtb == up) { v = ov; id = oi; }
            }
            sv[i] = v; si_[i] = id;
        }
        __syncthreads();
    }

    // tail: write sorted arrays + exp caches + scalar scans
    const int base = tid * 4;
    float eaz[4], ebz[4];
    #pragma unroll
    for (int q = 0; q < 4; q++) {
        float t = sv[base + q];
        eaz[q] = __expf(t); ebz[q] = __expf(ALPHA * t);
        ts[base + q] = t; pm[base + q] = si_[base + q];
        ea_o[base + q] = eaz[q]; eb_o[base + q] = ebz[q];
    }
    float sumB = ebz[0] + ebz[1] + ebz[2] + ebz[3];
    float sumA = eaz[0] + eaz[1] + eaz[2] + eaz[3];
    float inclB = sumB;
    #pragma unroll
    for (int o = 1; o < 32; o <<= 1) { float t = __shfl_up_sync(0xffffffffu, inclB, o); if (lane >= o) inclB += t; }
    float sufA = sumA;
    #pragma unroll
    for (int o = 1; o < 32; o <<= 1) { float t = __shfl_down_sync(0xffffffffu, sufA, o); if (lane + o < 32) sufA += t; }
    if (lane == 31) wtB[w] = inclB;
    if (lane == 0)  wtA[w] = sufA;
    __syncthreads();
    float prevB = 0.f, aftA = 0.f;
    for (int ww = 0; ww < 32; ww++) { if (ww < w) prevB += wtB[ww]; if (ww > w) aftA += wtA[ww]; }
    float exB = prevB + inclB - sumB;   // sum of eb before this chunk
    float sfA = aftA + sufA;            // sum of ea from this chunk (inclusive)
    #pragma unroll
    for (int q = 0; q < 4; q++) {
        fs_[base + q] = exB;
        es_[base + q] = sfA;
        exB += ebz[q];
        sfA -= eaz[q];
    }
    if (tid == 1023) { fs_[4096] = exB; es_[4096] = 0.f; }
}

__global__ __launch_bounds__(1024) void sort1_kernel() {
    __shared__ float sv[4096]; __shared__ int si_[4096];
    __shared__ float wtA[32], wtB[32];
    const int h = blockIdx.x;
    sortex_body(sv, si_, wtA, wtB, g_sdst + h * NN, g_ts1 + h * NN, g_pm1 + h * NN,
                g_e1a + h * NN, g_e1b + h * NN, g_es1 + h * NP1, g_fs1 + h * NP1);
}
__global__ __launch_bounds__(1024) void sort2_kernel() {
    __shared__ float sv[4096]; __shared__ int si_[4096];
    __shared__ float wtA[32], wtB[32];
    sortex_body(sv, si_, wtA, wtB, g_s2dst, g_ts2, g_pm2, g_e2a, g_e2b, g_es2, g_fs2);
}

// ============================================================
// scan1: rank-tile blocks, fully coalesced [r][c] E/F layout.
// Block (tt,h): ranks [tt*128, +128). 256 thr = 64 cols x 4 subs.
// Three-phase: sub totals -> intra-tile offsets -> prefix/suffix
// writes. Tile totals out for the cross-tile offsets kernel.
// ============================================================
__global__ void scan1_kernel() {
    const int h  = blockIdx.y;
    const int tt = blockIdx.x;
    const int tid = threadIdx.x;
    const int c = tid & 63, sub = tid >> 6;
    const int kb = tt * TILE + sub * 32;
    const int hb = h * NN;
    __shared__ float sA[4][64], sB[4][64];

    float aT = 0.f, bT = 0.f;
    #pragma unroll 4
    for (int m = 0; m < 32; m++) {
        int idx = kb + m;
        float hv = g_h1[(hb + g_pm1[hb + idx]) * NHID + c];
        aT += g_e1a[hb + idx] * hv;
        bT += g_e1b[hb + idx] * hv;
    }
    sA[sub][c] = aT; sB[sub][c] = bT;
    __syncthreads();
    float offb = 0.f, offa = 0.f;
    #pragma unroll
    for (int s = 0; s < 4; s++) { if (s < sub) offb += sB[s][c]; if (s > sub) offa += sA[s][c]; }

    float fb = offb;
    #pragma unroll 4
    for (int m = 0; m < 32; m++) {
        int idx = kb + m;
        float hv = g_h1[(hb + g_pm1[hb + idx]) * NHID + c];
        g_F1[(h * NP1 + idx) * NHID + c] = fb;
        fb += g_e1b[hb + idx] * hv;
    }
    float ea = offa;
    #pragma unroll 4
    for (int m = 31; m >= 0; m--) {
        int idx = kb + m;
        float hv = g_h1[(hb + g_pm1[hb + idx]) * NHID + c];
        ea += g_e1a[hb + idx] * hv;
        g_E1[(h * NP1 + idx) * NHID + c] = ea;
    }
    if (sub == 0) {
        g_totA[(h * NT + tt) * NHID + c] = sA[0][c] + sA[1][c] + sA[2][c] + sA[3][c];
        g_totB[(h * NT + tt) * NHID + c] = sB[0][c] + sB[1][c] + sB[2][c] + sB[3][c];
    }
}

// cross-tile offsets + zero pad row 4096
__global__ void off1_kernel() {
    const int h = blockIdx.x, c = threadIdx.x;
    float acc = 0.f;
    for (int tt = 0; tt < NT; tt++) {
        g_offF[(h * (NT + 1) + tt) * NHID + c] = acc;
        acc += g_totB[(h * NT + tt) * NHID + c];
    }
    g_offF[(h * (NT + 1) + NT) * NHID + c] = acc;
    acc = 0.f;
    g_offE[(h * (NT + 1) + NT) * NHID + c] = 0.f;
    for (int tt = NT - 1; tt >= 0; tt--) {
        g_offE[(h * (NT + 1) + tt) * NHID + c] = acc;
        acc += g_totA[(h * NT + tt) * NHID + c];
    }
    g_E1[(h * NP1 + NN) * NHID + c] = 0.f;
    g_F1[(h * NP1 + NN) * NHID + c] = 0.f;
}

// ============================================================
// row1: parallel-lane binary searches (lanes 0..7 search the
// warp's 8 rows concurrently), then batched gathers (4 rows of
// loads in flight) -> elu -> xc.
// ============================================================
__global__ void row1_kernel() {
    __shared__ float st[4096];
    const int h = blockIdx.y;
    const int warp = threadIdx.x >> 5, lane = threadIdx.x & 31;
    for (int q = threadIdx.x; q < 4096; q += 256) st[q] = g_ts1[h * NN + q];
    __syncthreads();
    const int rbase = blockIdx.x * 64 + warp * 8;
    const float s_l = g_ssrc[h * NN + rbase + (lane & 7)];
    const float w1_l = __expf(s_l), w2_l = __expf(ALPHA * s_l);
    int lo = 0, hi = 4096; const float thr = -s_l;
    while (lo < hi) { int mid = (lo + hi) >> 1; if (st[mid] <= thr) lo = mid + 1; else hi = mid; }

    #pragma unroll
    for (int half = 0; half < 2; half++) {
        int rA[4]; float w1A[4], w2A[4];
        #pragma unroll
        for (int q = 0; q < 4; q++) {
            int rr = half * 4 + q;
            rA[q]  = __shfl_sync(0xffffffffu, lo, rr);
            w1A[q] = __shfl_sync(0xffffffffu, w1_l, rr);
            w2A[q] = __shfl_sync(0xffffffffu, w2_l, rr);
        }
        float e0[4], e1v[4], f0[4], f1v[4], oe0[4], oe1[4], of0[4], of1[4], dn1[4], dn2[4];
        #pragma unroll
        for (int q = 0; q < 4; q++) {
            int r = rA[q], tt = r >> 7;
            const float* E  = &g_E1[(h * NP1 + r) * NHID];
            const float* F  = &g_F1[(h * NP1 + r) * NHID];
            const float* OE = &g_offE[(h * (NT + 1) + tt) * NHID];
            const float* OF = &g_offF[(h * (NT + 1) + tt) * NHID];
            e0[q] = E[lane];  e1v[q] = E[lane + 32];
            f0[q] = F[lane];  f1v[q] = F[lane + 32];
            oe0[q] = OE[lane]; oe1[q] = OE[lane + 32];
            of0[q] = OF[lane]; of1[q] = OF[lane + 32];
            dn1[q] = g_es1[h * NP1 + r]; dn2[q] = g_fs1[h * NP1 + r];
        }
        #pragma unroll
        for (int q = 0; q < 4; q++) {
            int i = rbase + half * 4 + q;
            float inv = 1.f / (w1A[q] * dn1[q] + w2A[q] * dn2[q]);
            float va = (w1A[q] * (e0[q]  + oe0[q]) + w2A[q] * (f0[q]  + of0[q])) * inv;
            float vb = (w1A[q] * (e1v[q] + oe1[q]) + w2A[q] * (f1v[q] + of1[q])) * inv;
            g_xc[i * (NH * NHID) + h * NHID + lane]      = elu1(va);
            g_xc[i * (NH * NHID) + h * NHID + lane + 32] = elu1(vb);
        }
    }
}

// ============================================================
// gemm2: h2 = xc @ Wo + layer-2 score dots (unchanged)
// ============================================================
__global__ void gemm2_kernel(const float* __restrict__ Wo, const float* __restrict__ ao) {
    __shared__ __align__(16) float sxcT[32][68];
    __shared__ __align__(16) float sWo[32][20];
    __shared__ __align__(16) float sh2s[64][17];
    const int r0 = blockIdx.x * 64;
    const int tid = threadIdx.x;
    const int c4 = tid & 3, r = tid >> 2;
    float acc[4] = {};

    for (int k0 = 0; k0 < NFEAT; k0 += 32) {
        __syncthreads();
        #pragma unroll
        for (int i = tid; i < 2048; i += 256) {
            int k = i & 31, rr = i >> 5;
            sxcT[k][rr] = g_xc[(r0 + rr) * NFEAT + k0 + k];
        }
        #pragma unroll
        for (int i = tid; i < 512; i += 256) {
            int k = i >> 4, c = i & 15;
            sWo[k][c] = Wo[(k0 + k) * NCLS + c];
        }
        __syncthreads();
        #pragma unroll
        for (int k = 0; k < 32; k++) {
            float a = sxcT[k][r];
            float4 b = *(const float4*)&sWo[k][c4 * 4];
            acc[0] += a * b.x; acc[1] += a * b.y; acc[2] += a * b.z; acc[3] += a * b.w;
        }
    }
    *(float4*)&g_h2[(r0 + r) * NCLS + c4 * 4] = make_float4(acc[0], acc[1], acc[2], acc[3]);
    sh2s[r][c4 * 4 + 0] = acc[0];
    sh2s[r][c4 * 4 + 1] = acc[1];
    sh2s[r][c4 * 4 + 2] = acc[2];
    sh2s[r][c4 * 4 + 3] = acc[3];
    __syncthreads();
    if (tid < 64) {
        float ss = 0.f, sd = 0.f;
        #pragma unroll
        for (int c = 0; c < NCLS; c++) {
            float hv = sh2s[tid][c];
            ss += hv * ao[c];
            sd += hv * ao[NCLS + c];
        }
        g_s2src[r0 + tid] = ss;
        g_s2dst[r0 + tid] = sd;
    }
}

// ============================================================
// scan2: per-column scans for layer 2 (small; chunk-offset scan)
// ============================================================
__device__ __forceinline__ void chunk_offsets(const float* totA, const float* totB,
                                              float* offA, float* offB, int tid) {
    if (tid < 32) {
        float pb[8], pa[8];
        float sb = 0.f, sa = 0.f;
        #pragma unroll
        for (int j = 0; j < 8; j++) { sb += totB[tid * 8 + j]; pb[j] = sb; }
        #pragma unroll
        for (int j = 7; j >= 0; j--) { sa += totA[tid * 8 + j]; pa[j] = sa; }
        float eb = sb;
        #pragma unroll
        for (int o = 1; o < 32; o <<= 1) {
            float t = __shfl_up_sync(0xffffffffu, eb, o);
            if (tid >= o) eb += t;
        }
        eb -= sb;
        float ea = sa;
        #pragma unroll
        for (int o = 1; o < 32; o <<= 1) {
            float t = __shfl_down_sync(0xffffffffu, ea, o);
            if (tid + o < 32) ea += t;
        }
        ea -= sa;
        #pragma unroll
        for (int j = 0; j < 8; j++) {
            offB[tid * 8 + j + 1] = eb + pb[j];
            offA[tid * 8 + j]     = ea + pa[j];
        }
        if (tid == 0)  offB[0]   = 0.f;
        if (tid == 31) offA[256] = 0.f;
    }
}

__global__ void scan2_kernel() {
    const int c = blockIdx.x;   // 0..NCLS-1
    const int tid = threadIdx.x;
    __shared__ float totA[256], totB[256];
    __shared__ float offA[257], offB[257];
    float a_loc[16], b_loc[16];
    const int base = tid * 16;
    #pragma unroll
    for (int q = 0; q < 16; q++) {
        int k = base + q;
        float hv = g_h2[g_pm2[k] * NCLS + c];
        a_loc[q] = g_e2a[k] * hv;
        b_loc[q] = g_e2b[k] * hv;
    }
    #pragma unroll
    for (int q = 1; q < 16; q++) b_loc[q] += b_loc[q - 1];
    #pragma unroll
    for (int q = 14; q >= 0; q--) a_loc[q] += a_loc[q + 1];
    totB[tid] = b_loc[15]; totA[tid] = a_loc[0];
    __syncthreads();
    chunk_offsets(totA, totB, offA, offB, tid);
    __syncthreads();
    const float ob = offB[tid];
    const float oa = offA[tid + 1];
    float* E = g_E2 + c;
    float* F = g_F2 + c;
    #pragma unroll
    for (int q = 0; q < 16; q++) {
        E[(base + q) * NCLS]     = a_loc[q] + oa;
        F[(base + q + 1) * NCLS] = b_loc[q] + ob;
    }
    if (tid == 0)   F[0] = 0.f;
    if (tid == 255) E[NN * NCLS] = 0.f;
}

// ============================================================
// row2: parallel-lane searches + combine + elu + log_softmax
// ============================================================
__global__ void row2_kernel(float* __restrict__ out) {
    __shared__ float st[4096];
    const int warp = threadIdx.x >> 5, lane = threadIdx.x & 31;
    for (int q = threadIdx.x; q < 4096; q += 256) st[q] = g_ts2[q];
    __syncthreads();
    const int rbase = blockIdx.x * 64 + warp * 8;
    const float s_l = g_s2src[rbase + (lane & 7)];
    const float w1_l = __expf(s_l), w2_l = __expf(ALPHA * s_l);
    int lo = 0, hi = 4096; const float thr = -s_l;
    while (lo < hi) { int mid = (lo + hi) >> 1; if (st[mid] <= thr) lo = mid + 1; else hi = mid; }

    #pragma unroll
    for (int rr = 0; rr < 8; rr++) {
        const int i = rbase + rr;
        const int r  = __shfl_sync(0xffffffffu, lo, rr);
        const float w1 = __shfl_sync(0xffffffffu, w1_l, rr);
        const float w2 = __shfl_sync(0xffffffffu, w2_l, rr);
        const float den = w1 * g_es2[r] + w2 * g_fs2[r];
        const float invden = 1.f / den;
        float v = -1e30f;
        if (lane < NCLS)
            v = elu1((w1 * g_E2[r * NCLS + lane] + w2 * g_F2[r * NCLS + lane]) * invden);
        float m = v;
        #pragma unroll
        for (int o = 8; o; o >>= 1) m = fmaxf(m, __shfl_xor_sync(0xffffffffu, m, o));
        float s = __expf(v - m);
        #pragma unroll
        for (int o = 8; o; o >>= 1) s += __shfl_xor_sync(0xffffffffu, s, o);
        const float lse = m + __logf(s);
        if (lane < NCLS) out[i * NCLS + lane] = v - lse;
    }
}

// ============================================================
extern "C" void kernel_launch(void* const* d_in, const int* in_sizes, int n_in,
                              void* d_out, int out_size) {
    const float* x  = (const float*)d_in[0];
    const float* Wh = (const float*)d_in[1];
    const float* ah = (const float*)d_in[2];
    const float* Wo = (const float*)d_in[3];
    const float* ao = (const float*)d_in[4];
    float* out = (float*)d_out;

    gemm1_kernel<<<dim3(NN / 128, 4), 256>>>(x, Wh, ah);
    sort1_kernel<<<NH, 1024>>>();
    scan1_kernel<<<dim3(NT, NH), 256>>>();
    off1_kernel<<<NH, 64>>>();
    row1_kernel<<<dim3(NN / 64, NH), 256>>>();
    gemm2_kernel<<<NN / 64, 256>>>(Wo, ao);
    sort2_kernel<<<1, 1024>>>();
    scan2_kernel<<<NCLS, 256>>>();
    row2_kernel<<<NN / 64, 256>>>(out);
}

// round 8
// speedup vs baseline: 1.2843x; 1.0505x over previous
#include <cuda_runtime.h>
#include <cstdint>

#define NN    4096
#define NP1   4097
#define NFEAT 512
#define NHID  64
#define NCLS  16
#define NH    8
#define ALPHA 0.2f
#define TILE  128
#define NT    (NN / TILE)   // 32

// ---- scratch (device globals; no allocation allowed) ----
__device__ __align__(16) float g_h1[NH * NN * NHID];
__device__ float g_ssrc[NH * NN];
__device__ float g_sdst[NH * NN];
__device__ __align__(16) float g_xc[NN * NH * NHID];
__device__ __align__(16) float g_h2[NN * NCLS];
__device__ float g_s2src[NN];
__device__ float g_s2dst[NN];

// sorted scores + permutations + exp caches (written by sort tails)
__device__ float g_ts1[NH * NN];
__device__ int   g_pm1[NH * NN];
__device__ float g_e1a[NH * NN];
__device__ float g_e1b[NH * NN];
__device__ float g_ts2[NN];
__device__ int   g_pm2[NN];
__device__ float g_e2a[NN];
__device__ float g_e2b[NN];

// layer-1 scans, [h][r][c] row-contiguous; within-tile values + cross-tile offsets
__device__ __align__(16) float g_E1[NH * NP1 * NHID];
__device__ __align__(16) float g_F1[NH * NP1 * NHID];
__device__ float g_totA[NH * NT * NHID];
__device__ float g_totB[NH * NT * NHID];
__device__ float g_offE[NH * (NT + 1) * NHID];
__device__ float g_offF[NH * (NT + 1) * NHID];
__device__ float g_es1[NH * NP1];
__device__ float g_fs1[NH * NP1];

// layer-2 scans
__device__ float g_E2[NP1 * NCLS];
__device__ float g_F2[NP1 * NCLS];
__device__ float g_es2[NP1];
__device__ float g_fs2[NP1];

__device__ __forceinline__ float elu1(float v) { return v > 0.f ? v : __expf(v) - 1.f; }

// packed f32x2 helpers (sm_103a FFMA2 path)
__device__ __forceinline__ unsigned long long pack_dup(float a) {
    unsigned long long r;
    asm("mov.b64 %0, {%1, %1};" : "=l"(r) : "r"(__float_as_uint(a)));
    return r;
}
__device__ __forceinline__ void fma2(unsigned long long& acc, unsigned long long a, unsigned long long b) {
    asm("fma.rn.f32x2 %0, %1, %2, %0;" : "+l"(acc) : "l"(a), "l"(b));
}

// ============================================================
// Kernel 1: h1 = x @ Wh (fused per-row score dots in epilogue)
// ============================================================
__global__ __launch_bounds__(256) void gemm1_kernel(const float* __restrict__ x,
                                                    const float* __restrict__ Wh,
                                                    const float* __restrict__ ah) {
    __shared__ __align__(16) float sxT[16][132];
    __shared__ __align__(16) float sW[16][132];
    const int r0 = blockIdx.x * 128;
    const int by = blockIdx.y;
    const int tid = threadIdx.x;
    const int tx = tid & 15, ty = tid >> 4;

    unsigned long long acc[8][4] = {};

    float4 px0, px1, pw0, pw1;
    {
        int e0 = tid, e1 = tid + 256;
        int r_ = e0 >> 2, kq = e0 & 3;
        px0 = *(const float4*)&x[(r0 + r_) * NFEAT + kq * 4];
        r_ = e1 >> 2; kq = e1 & 3;
        px1 = *(const float4*)&x[(r0 + r_) * NFEAT + kq * 4];
        int k_ = e0 >> 5, cq = e0 & 31;
        pw0 = *(const float4*)&Wh[((2 * by + (cq >> 4)) * NFEAT + k_) * NHID + (cq & 15) * 4];
        k_ = e1 >> 5; cq = e1 & 31;
        pw1 = *(const float4*)&Wh[((2 * by + (cq >> 4)) * NFEAT + k_) * NHID + (cq & 15) * 4];
    }

    for (int kt = 0; kt < NFEAT / 16; kt++) {
        __syncthreads();
        {
            int e0 = tid, e1 = tid + 256;
            int r_ = e0 >> 2, kq = e0 & 3;
            sxT[kq * 4 + 0][r_] = px0.x; sxT[kq * 4 + 1][r_] = px0.y;
            sxT[kq * 4 + 2][r_] = px0.z; sxT[kq * 4 + 3][r_] = px0.w;
            r_ = e1 >> 2; kq = e1 & 3;
            sxT[kq * 4 + 0][r_] = px1.x; sxT[kq * 4 + 1][r_] = px1.y;
            sxT[kq * 4 + 2][r_] = px1.z; sxT[kq * 4 + 3][r_] = px1.w;
            int k_ = e0 >> 5, cq = e0 & 31;
            *(float4*)&sW[k_][cq * 4] = pw0;
            k_ = e1 >> 5; cq = e1 & 31;
            *(float4*)&sW[k_][cq * 4] = pw1;
        }
        __syncthreads();
        if (kt + 1 < NFEAT / 16) {
            int k0 = (kt + 1) * 16;
            int e0 = tid, e1 = tid + 256;
            int r_ = e0 >> 2, kq = e0 & 3;
            px0 = *(const float4*)&x[(r0 + r_) * NFEAT + k0 + kq * 4];
            r_ = e1 >> 2; kq = e1 & 3;
            px1 = *(const float4*)&x[(r0 + r_) * NFEAT + k0 + kq * 4];
            int k_ = e0 >> 5, cq = e0 & 31;
            pw0 = *(const float4*)&Wh[((2 * by + (cq >> 4)) * NFEAT + k0 + k_) * NHID + (cq & 15) * 4];
            k_ = e1 >> 5; cq = e1 & 31;
            pw1 = *(const float4*)&Wh[((2 * by + (cq >> 4)) * NFEAT + k0 + k_) * NHID + (cq & 15) * 4];
        }
        #pragma unroll
        for (int k = 0; k < 16; k++) {
            float4 a03 = *(const float4*)&sxT[k][ty * 8];
            float4 a47 = *(const float4*)&sxT[k][ty * 8 + 4];
            ulonglong2 bA = *(const ulonglong2*)&sW[k][tx * 8];
            ulonglong2 bB = *(const ulonglong2*)&sW[k][tx * 8 + 4];
            unsigned long long pa[8];
            pa[0] = pack_dup(a03.x); pa[1] = pack_dup(a03.y);
            pa[2] = pack_dup(a03.z); pa[3] = pack_dup(a03.w);
            pa[4] = pack_dup(a47.x); pa[5] = pack_dup(a47.y);
            pa[6] = pack_dup(a47.z); pa[7] = pack_dup(a47.w);
            #pragma unroll
            for (int i = 0; i < 8; i++) {
                fma2(acc[i][0], pa[i], bA.x);
                fma2(acc[i][1], pa[i], bA.y);
                fma2(acc[i][2], pa[i], bB.x);
                fma2(acc[i][3], pa[i], bB.y);
            }
        }
    }

    const int head = 2 * by + (tx >> 3);
    const int cb = (tx * 8) & 63;
    float4 as0 = *(const float4*)&ah[head * 2 * NHID + cb];
    float4 as1 = *(const float4*)&ah[head * 2 * NHID + cb + 4];
    float4 ad0 = *(const float4*)&ah[head * 2 * NHID + NHID + cb];
    float4 ad1 = *(const float4*)&ah[head * 2 * NHID + NHID + cb + 4];
    #pragma unroll
    for (int i = 0; i < 8; i++) {
        int r = r0 + ty * 8 + i;
        float4 lo, hi;
        lo.x = __uint_as_float((unsigned)acc[i][0]);  lo.y = __uint_as_float((unsigned)(acc[i][0] >> 32));
        lo.z = __uint_as_float((unsigned)acc[i][1]);  lo.w = __uint_as_float((unsigned)(acc[i][1] >> 32));
        hi.x = __uint_as_float((unsigned)acc[i][2]);  hi.y = __uint_as_float((unsigned)(acc[i][2] >> 32));
        hi.z = __uint_as_float((unsigned)acc[i][3]);  hi.w = __uint_as_float((unsigned)(acc[i][3] >> 32));
        *(float4*)&g_h1[(head * NN + r) * NHID + cb]     = lo;
        *(float4*)&g_h1[(head * NN + r) * NHID + cb + 4] = hi;
        float ss = lo.x*as0.x + lo.y*as0.y + lo.z*as0.z + lo.w*as0.w
                 + hi.x*as1.x + hi.y*as1.y + hi.z*as1.z + hi.w*as1.w;
        float sd = lo.x*ad0.x + lo.y*ad0.y + lo.z*ad0.z + lo.w*ad0.w
                 + hi.x*ad1.x + hi.y*ad1.y + hi.z*ad1.z + hi.w*ad1.w;
        #pragma unroll
        for (int o = 4; o; o >>= 1) {
            ss += __shfl_xor_sync(0xffffffffu, ss, o);
            sd += __shfl_xor_sync(0xffffffffu, sd, o);
        }
        if ((tx & 7) == 0) {
            g_ssrc[head * NN + r] = ss;
            g_sdst[head * NN + r] = sd;
        }
    }
}

// ============================================================
// Bitonic sort (warp-local shfl for j<=16) + fused exp caches
// + fused scalar prefix/suffix scans (es/fs) in the tail.
// ============================================================
__device__ void sortex_body(float* sv, int* si_, float* wtA, float* wtB,
                            const float* __restrict__ src,
                            float* ts, int* pm, float* ea_o, float* eb_o,
                            float* es_, float* fs_) {
    const int tid = threadIdx.x, lane = tid & 31, w = tid >> 5;
    for (int i = tid; i < 4096; i += 1024) { sv[i] = src[i]; si_[i] = i; }
    __syncthreads();

    #pragma unroll
    for (int gg = 0; gg < 4; gg++) {
        int g = w * 4 + gg, i = g * 32 + lane;
        float v = sv[i]; int id = si_[i];
        #pragma unroll
        for (int k = 2; k <= 32; k <<= 1) {
            bool up = ((i & k) == 0);
            #pragma unroll
            for (int j = k >> 1; j; j >>= 1) {
                float ov = __shfl_xor_sync(0xffffffffu, v, j);
                int   oi = __shfl_xor_sync(0xffffffffu, id, j);
                bool lower = (lane & j) == 0;
                bool agtb = lower ? (v > ov) : (ov > v);
                if (agtb == up) { v = ov; id = oi; }
            }
        }
        sv[i] = v; si_[i] = id;
    }
    __syncthreads();

    for (int k = 64; k <= 4096; k <<= 1) {
        for (int j = k >> 1; j >= 32; j >>= 1) {
            #pragma unroll
            for (int q = 0; q < 4; q++) {
                int i = tid + q * 1024;
                int ixj = i ^ j;
                if (ixj > i) {
                    bool up = ((i & k) == 0);
                    float a = sv[i], b = sv[ixj];
                    if ((a > b) == up) {
                        sv[i] = b; sv[ixj] = a;
                        int t = si_[i]; si_[i] = si_[ixj]; si_[ixj] = t;
                    }
                }
            }
            __syncthreads();
        }
        #pragma unroll
        for (int gg = 0; gg < 4; gg++) {
            int g = w * 4 + gg, i = g * 32 + lane;
            float v = sv[i]; int id = si_[i];
            bool up = ((i & k) == 0);
            #pragma unroll
            for (int j = 16; j; j >>= 1) {
                float ov = __shfl_xor_sync(0xffffffffu, v, j);
                int   oi = __shfl_xor_sync(0xffffffffu, id, j);
                bool lower = (lane & j) == 0;
                bool agtb = lower ? (v > ov) : (ov > v);
                if (agtb == up) { v = ov; id = oi; }
            }
            sv[i] = v; si_[i] = id;
        }
        __syncthreads();
    }

    // tail: write sorted arrays + exp caches + scalar scans
    const int base = tid * 4;
    float eaz[4], ebz[4];
    #pragma unroll
    for (int q = 0; q < 4; q++) {
        float t = sv[base + q];
        eaz[q] = __expf(t); ebz[q] = __expf(ALPHA * t);
        ts[base + q] = t; pm[base + q] = si_[base + q];
        ea_o[base + q] = eaz[q]; eb_o[base + q] = ebz[q];
    }
    float sumB = ebz[0] + ebz[1] + ebz[2] + ebz[3];
    float sumA = eaz[0] + eaz[1] + eaz[2] + eaz[3];
    float inclB = sumB;
    #pragma unroll
    for (int o = 1; o < 32; o <<= 1) { float t = __shfl_up_sync(0xffffffffu, inclB, o); if (lane >= o) inclB += t; }
    float sufA = sumA;
    #pragma unroll
    for (int o = 1; o < 32; o <<= 1) { float t = __shfl_down_sync(0xffffffffu, sufA, o); if (lane + o < 32) sufA += t; }
    if (lane == 31) wtB[w] = inclB;
    if (lane == 0)  wtA[w] = sufA;
    __syncthreads();
    float prevB = 0.f, aftA = 0.f;
    for (int ww = 0; ww < 32; ww++) { if (ww < w) prevB += wtB[ww]; if (ww > w) aftA += wtA[ww]; }
    float exB = prevB + inclB - sumB;
    float sfA = aftA + sufA;
    #pragma unroll
    for (int q = 0; q < 4; q++) {
        fs_[base + q] = exB;
        es_[base + q] = sfA;
        exB += ebz[q];
        sfA -= eaz[q];
    }
    if (tid == 1023) { fs_[4096] = exB; es_[4096] = 0.f; }
}

__global__ __launch_bounds__(1024) void sort1_kernel() {
    __shared__ float sv[4096]; __shared__ int si_[4096];
    __shared__ float wtA[32], wtB[32];
    const int h = blockIdx.x;
    sortex_body(sv, si_, wtA, wtB, g_sdst + h * NN, g_ts1 + h * NN, g_pm1 + h * NN,
                g_e1a + h * NN, g_e1b + h * NN, g_es1 + h * NP1, g_fs1 + h * NP1);
}
__global__ __launch_bounds__(1024) void sort2_kernel() {
    __shared__ float sv[4096]; __shared__ int si_[4096];
    __shared__ float wtA[32], wtB[32];
    sortex_body(sv, si_, wtA, wtB, g_s2dst, g_ts2, g_pm2, g_e2a, g_e2b, g_es2, g_fs2);
}

// ============================================================
// scan1: rank-tile blocks, fully coalesced [r][c] E/F layout.
// ============================================================
__global__ void scan1_kernel() {
    const int h  = blockIdx.y;
    const int tt = blockIdx.x;
    const int tid = threadIdx.x;
    const int c = tid & 63, sub = tid >> 6;
    const int kb = tt * TILE + sub * 32;
    const int hb = h * NN;
    __shared__ float sA[4][64], sB[4][64];

    float aT = 0.f, bT = 0.f;
    #pragma unroll 4
    for (int m = 0; m < 32; m++) {
        int idx = kb + m;
        float hv = g_h1[(hb + g_pm1[hb + idx]) * NHID + c];
        aT += g_e1a[hb + idx] * hv;
        bT += g_e1b[hb + idx] * hv;
    }
    sA[sub][c] = aT; sB[sub][c] = bT;
    __syncthreads();
    float offb = 0.f, offa = 0.f;
    #pragma unroll
    for (int s = 0; s < 4; s++) { if (s < sub) offb += sB[s][c]; if (s > sub) offa += sA[s][c]; }

    float fb = offb;
    #pragma unroll 4
    for (int m = 0; m < 32; m++) {
        int idx = kb + m;
        float hv = g_h1[(hb + g_pm1[hb + idx]) * NHID + c];
        g_F1[(h * NP1 + idx) * NHID + c] = fb;
        fb += g_e1b[hb + idx] * hv;
    }
    float ea = offa;
    #pragma unroll 4
    for (int m = 31; m >= 0; m--) {
        int idx = kb + m;
        float hv = g_h1[(hb + g_pm1[hb + idx]) * NHID + c];
        ea += g_e1a[hb + idx] * hv;
        g_E1[(h * NP1 + idx) * NHID + c] = ea;
    }
    if (sub == 0) {
        g_totA[(h * NT + tt) * NHID + c] = sA[0][c] + sA[1][c] + sA[2][c] + sA[3][c];
        g_totB[(h * NT + tt) * NHID + c] = sB[0][c] + sB[1][c] + sB[2][c] + sB[3][c];
    }
}

// ============================================================
// off1: cross-tile offsets via warp shuffle scans.
// Was: 2 serial 32-iteration dependent-LDG loops on 8x64 threads
// (31.8us latency-bound, all pipes ~0%). Now: lane = tile index,
// one coalesced load round + 5-round shfl scans. grid=NH, 1024thr:
// warp w owns cols {2w, 2w+1}.
// ============================================================
__global__ __launch_bounds__(1024) void off1_kernel() {
    const int h = blockIdx.x;
    const int lane = threadIdx.x & 31, w = threadIdx.x >> 5;
    #pragma unroll
    for (int cc = 0; cc < 2; cc++) {
        const int c = w * 2 + cc;
        const float a = g_totA[(h * NT + lane) * NHID + c];
        const float b = g_totB[(h * NT + lane) * NHID + c];
        // inclusive prefix of b over lanes (tile order)
        float ib = b;
        #pragma unroll
        for (int o = 1; o < 32; o <<= 1) {
            float t = __shfl_up_sync(0xffffffffu, ib, o);
            if (lane >= o) ib += t;
        }
        // inclusive suffix of a over lanes
        float sa = a;
        #pragma unroll
        for (int o = 1; o < 32; o <<= 1) {
            float t = __shfl_down_sync(0xffffffffu, sa, o);
            if (lane + o < 32) sa += t;
        }
        g_offF[(h * (NT + 1) + lane) * NHID + c] = ib - b;   // sum of tiles before
        g_offE[(h * (NT + 1) + lane) * NHID + c] = sa - a;   // sum of tiles after
        if (lane == 31) {
            g_offF[(h * (NT + 1) + NT) * NHID + c] = ib;     // total
            g_offE[(h * (NT + 1) + NT) * NHID + c] = 0.f;
        }
        if (lane == 0) {
            g_E1[(h * NP1 + NN) * NHID + c] = 0.f;
            g_F1[(h * NP1 + NN) * NHID + c] = 0.f;
        }
    }
}

// ============================================================
// row1: parallel-lane binary searches, batched gathers -> xc.
// ============================================================
__global__ void row1_kernel() {
    __shared__ float st[4096];
    const int h = blockIdx.y;
    const int warp = threadIdx.x >> 5, lane = threadIdx.x & 31;
    for (int q = threadIdx.x; q < 4096; q += 256) st[q] = g_ts1[h * NN + q];
    __syncthreads();
    const int rbase = blockIdx.x * 64 + warp * 8;
    const float s_l = g_ssrc[h * NN + rbase + (lane & 7)];
    const float w1_l = __expf(s_l), w2_l = __expf(ALPHA * s_l);
    int lo = 0, hi = 4096; const float thr = -s_l;
    while (lo < hi) { int mid = (lo + hi) >> 1; if (st[mid] <= thr) lo = mid + 1; else hi = mid; }

    #pragma unroll
    for (int half = 0; half < 2; half++) {
        int rA[4]; float w1A[4], w2A[4];
        #pragma unroll
        for (int q = 0; q < 4; q++) {
            int rr = half * 4 + q;
            rA[q]  = __shfl_sync(0xffffffffu, lo, rr);
            w1A[q] = __shfl_sync(0xffffffffu, w1_l, rr);
            w2A[q] = __shfl_sync(0xffffffffu, w2_l, rr);
        }
        float e0[4], e1v[4], f0[4], f1v[4], oe0[4], oe1[4], of0[4], of1[4], dn1[4], dn2[4];
        #pragma unroll
        for (int q = 0; q < 4; q++) {
            int r = rA[q], tt = r >> 7;
            const float* E  = &g_E1[(h * NP1 + r) * NHID];
            const float* F  = &g_F1[(h * NP1 + r) * NHID];
            const float* OE = &g_offE[(h * (NT + 1) + tt) * NHID];
            const float* OF = &g_offF[(h * (NT + 1) + tt) * NHID];
            e0[q] = E[lane];  e1v[q] = E[lane + 32];
            f0[q] = F[lane];  f1v[q] = F[lane + 32];
            oe0[q] = OE[lane]; oe1[q] = OE[lane + 32];
            of0[q] = OF[lane]; of1[q] = OF[lane + 32];
            dn1[q] = g_es1[h * NP1 + r]; dn2[q] = g_fs1[h * NP1 + r];
        }
        #pragma unroll
        for (int q = 0; q < 4; q++) {
            int i = rbase + half * 4 + q;
            float inv = 1.f / (w1A[q] * dn1[q] + w2A[q] * dn2[q]);
            float va = (w1A[q] * (e0[q]  + oe0[q]) + w2A[q] * (f0[q]  + of0[q])) * inv;
            float vb = (w1A[q] * (e1v[q] + oe1[q]) + w2A[q] * (f1v[q] + of1[q])) * inv;
            g_xc[i * (NH * NHID) + h * NHID + lane]      = elu1(va);
            g_xc[i * (NH * NHID) + h * NHID + lane + 32] = elu1(vb);
        }
    }
}

// ============================================================
// gemm2: h2 = xc @ Wo + layer-2 score dots
// ============================================================
__global__ void gemm2_kernel(const float* __restrict__ Wo, const float* __restrict__ ao) {
    __shared__ __align__(16) float sxcT[32][68];
    __shared__ __align__(16) float sWo[32][20];
    __shared__ __align__(16) float sh2s[64][17];
    const int r0 = blockIdx.x * 64;
    const int tid = threadIdx.x;
    const int c4 = tid & 3, r = tid >> 2;
    float acc[4] = {};

    for (int k0 = 0; k0 < NFEAT; k0 += 32) {
        __syncthreads();
        #pragma unroll
        for (int i = tid; i < 2048; i += 256) {
            int k = i & 31, rr = i >> 5;
            sxcT[k][rr] = g_xc[(r0 + rr) * NFEAT + k0 + k];
        }
        #pragma unroll
        for (int i = tid; i < 512; i += 256) {
            int k = i >> 4, c = i & 15;
            sWo[k][c] = Wo[(k0 + k) * NCLS + c];
        }
        __syncthreads();
        #pragma unroll
        for (int k = 0; k < 32; k++) {
            float a = sxcT[k][r];
            float4 b = *(const float4*)&sWo[k][c4 * 4];
            acc[0] += a * b.x; acc[1] += a * b.y; acc[2] += a * b.z; acc[3] += a * b.w;
        }
    }
    *(float4*)&g_h2[(r0 + r) * NCLS + c4 * 4] = make_float4(acc[0], acc[1], acc[2], acc[3]);
    sh2s[r][c4 * 4 + 0] = acc[0];
    sh2s[r][c4 * 4 + 1] = acc[1];
    sh2s[r][c4 * 4 + 2] = acc[2];
    sh2s[r][c4 * 4 + 3] = acc[3];
    __syncthreads();
    if (tid < 64) {
        float ss = 0.f, sd = 0.f;
        #pragma unroll
        for (int c = 0; c < NCLS; c++) {
            float hv = sh2s[tid][c];
            ss += hv * ao[c];
            sd += hv * ao[NCLS + c];
        }
        g_s2src[r0 + tid] = ss;
        g_s2dst[r0 + tid] = sd;
    }
}

// ============================================================
// scan2: per-column scans for layer 2
// ============================================================
__device__ __forceinline__ void chunk_offsets(const float* totA, const float* totB,
                                              float* offA, float* offB, int tid) {
    if (tid < 32) {
        float pb[8], pa[8];
        float sb = 0.f, sa = 0.f;
        #pragma unroll
        for (int j = 0; j < 8; j++) { sb += totB[tid * 8 + j]; pb[j] = sb; }
        #pragma unroll
        for (int j = 7; j >= 0; j--) { sa += totA[tid * 8 + j]; pa[j] = sa; }
        float eb = sb;
        #pragma unroll
        for (int o = 1; o < 32; o <<= 1) {
            float t = __shfl_up_sync(0xffffffffu, eb, o);
            if (tid >= o) eb += t;
        }
        eb -= sb;
        float ea = sa;
        #pragma unroll
        for (int o = 1; o < 32; o <<= 1) {
            float t = __shfl_down_sync(0xffffffffu, ea, o);
            if (tid + o < 32) ea += t;
        }
        ea -= sa;
        #pragma unroll
        for (int j = 0; j < 8; j++) {
            offB[tid * 8 + j + 1] = eb + pb[j];
            offA[tid * 8 + j]     = ea + pa[j];
        }
        if (tid == 0)  offB[0]   = 0.f;
        if (tid == 31) offA[256] = 0.f;
    }
}

__global__ void scan2_kernel() {
    const int c = blockIdx.x;
    const int tid = threadIdx.x;
    __shared__ float totA[256], totB[256];
    __shared__ float offA[257], offB[257];
    float a_loc[16], b_loc[16];
    const int base = tid * 16;
    #pragma unroll
    for (int q = 0; q < 16; q++) {
        int k = base + q;
        float hv = g_h2[g_pm2[k] * NCLS + c];
        a_loc[q] = g_e2a[k] * hv;
        b_loc[q] = g_e2b[k] * hv;
    }
    #pragma unroll
    for (int q = 1; q < 16; q++) b_loc[q] += b_loc[q - 1];
    #pragma unroll
    for (int q = 14; q >= 0; q--) a_loc[q] += a_loc[q + 1];
    totB[tid] = b_loc[15]; totA[tid] = a_loc[0];
    __syncthreads();
    chunk_offsets(totA, totB, offA, offB, tid);
    __syncthreads();
    const float ob = offB[tid];
    const float oa = offA[tid + 1];
    float* E = g_E2 + c;
    float* F = g_F2 + c;
    #pragma unroll
    for (int q = 0; q < 16; q++) {
        E[(base + q) * NCLS]     = a_loc[q] + oa;
        F[(base + q + 1) * NCLS] = b_loc[q] + ob;
    }
    if (tid == 0)   F[0] = 0.f;
    if (tid == 255) E[NN * NCLS] = 0.f;
}

// ============================================================
// row2: parallel-lane searches + combine + elu + log_softmax
// ============================================================
__global__ void row2_kernel(float* __restrict__ out) {
    __shared__ float st[4096];
    const int warp = threadIdx.x >> 5, lane = threadIdx.x & 31;
    for (int q = threadIdx.x; q < 4096; q += 256) st[q] = g_ts2[q];
    __syncthreads();
    const int rbase = blockIdx.x * 64 + warp * 8;
    const float s_l = g_s2src[rbase + (lane & 7)];
    const float w1_l = __expf(s_l), w2_l = __expf(ALPHA * s_l);
    int lo = 0, hi = 4096; const float thr = -s_l;
    while (lo < hi) { int mid = (lo + hi) >> 1; if (st[mid] <= thr) lo = mid + 1; else hi = mid; }

    #pragma unroll
    for (int rr = 0; rr < 8; rr++) {
        const int i = rbase + rr;
        const int r  = __shfl_sync(0xffffffffu, lo, rr);
        const float w1 = __shfl_sync(0xffffffffu, w1_l, rr);
        const float w2 = __shfl_sync(0xffffffffu, w2_l, rr);
        const float den = w1 * g_es2[r] + w2 * g_fs2[r];
        const float invden = 1.f / den;
        float v = -1e30f;
        if (lane < NCLS)
            v = elu1((w1 * g_E2[r * NCLS + lane] + w2 * g_F2[r * NCLS + lane]) * invden);
        float m = v;
        #pragma unroll
        for (int o = 8; o; o >>= 1) m = fmaxf(m, __shfl_xor_sync(0xffffffffu, m, o));
        float s = __expf(v - m);
        #pragma unroll
        for (int o = 8; o; o >>= 1) s += __shfl_xor_sync(0xffffffffu, s, o);
        const float lse = m + __logf(s);
        if (lane < NCLS) out[i * NCLS + lane] = v - lse;
    }
}

// ============================================================
extern "C" void kernel_launch(void* const* d_in, const int* in_sizes, int n_in,
                              void* d_out, int out_size) {
    const float* x  = (const float*)d_in[0];
    const float* Wh = (const float*)d_in[1];
    const float* ah = (const float*)d_in[2];
    const float* Wo = (const float*)d_in[3];
    const float* ao = (const float*)d_in[4];
    float* out = (float*)d_out;

    gemm1_kernel<<<dim3(NN / 128, 4), 256>>>(x, Wh, ah);
    sort1_kernel<<<NH, 1024>>>();
    scan1_kernel<<<dim3(NT, NH), 256>>>();
    off1_kernel<<<NH, 1024>>>();
    row1_kernel<<<dim3(NN / 64, NH), 256>>>();
    gemm2_kernel<<<NN / 64, 256>>>(Wo, ao);
    sort2_kernel<<<1, 1024>>>();
    scan2_kernel<<<NCLS, 256>>>();
    row2_kernel<<<NN / 64, 256>>>(out);
}